// round 12
// baseline (speedup 1.0000x reference)
#include <cuda_runtime.h>
#include <cuda_fp16.h>

#define BATCH 16
#define C_IN  64
#define C_OUT 32
#define V_HI  163842
#define V_LO  40962
#define KNB   7

#define TILES ((V_LO + 255) / 256)   // 161 tiles of 256 vertices

// Precomputed neigh table: g_neigh8[v*8+k] = up_neigh[down[v]*7 + k], stride 8.
__device__ int g_neigh8[V_LO * 8];
// Precomputed h = W@x + b, fp16, layout (b, o, v). 42 MB scratch.
__device__ unsigned short g_h[(long long)BATCH * C_OUT * V_LO];

__global__ void build_neigh_kernel(const int* __restrict__ up_neigh,
                                   const int* __restrict__ down) {
    int v = blockIdx.x * blockDim.x + threadIdx.x;
    if (v >= V_LO) return;
    int dv = down[v];
    const int* src = up_neigh + (long long)dv * KNB;
#pragma unroll
    for (int k = 0; k < KNB; k++) g_neigh8[v * 8 + k] = src[k];
    g_neigh8[v * 8 + 7] = 0;
}

// GEMV producer: h[b,o,v] = bias[o] + sum_c W[o][c]*x[b][c][v], stored fp16.
// Pure streaming (x coalesced reads, h coalesced 2B stores), no atomics.
__global__ __launch_bounds__(256) void gemm_kernel(
    const float* __restrict__ x,
    const float* __restrict__ W,
    const float* __restrict__ bias)
{
    __shared__ float sW[C_IN][C_OUT + 1];
    __shared__ float sB[C_OUT];

    const int tid = threadIdx.x;
    const int b   = blockIdx.y;

    for (int i = tid; i < C_IN * C_OUT; i += 256) {
        int o = i / C_IN;
        int c = i % C_IN;
        sW[c][o] = W[i];
    }
    if (tid < C_OUT) sB[tid] = bias[tid];
    __syncthreads();

    const int v = blockIdx.x * 256 + tid;
    if (v >= V_LO) return;

    float h[C_OUT];
#pragma unroll
    for (int o = 0; o < C_OUT; o++) h[o] = sB[o];

    const float* xp = x + ((long long)b * C_IN) * V_LO + v;
#pragma unroll
    for (int c = 0; c < C_IN; c++) {
        float xc = __ldg(xp + (long long)c * V_LO);
#pragma unroll
        for (int o = 0; o < C_OUT; o++) h[o] = fmaf(xc, sW[c][o], h[o]);
    }

    unsigned short* hp = g_h + ((long long)b * C_OUT) * V_LO + v;
#pragma unroll
    for (int o = 0; o < C_OUT; o++) {
        hp[(long long)o * V_LO] = __half_as_ushort(__float2half_rn(h[o]));  // coalesced
    }
}

// Load-only scatter: per thread (one vertex, all 32 channels):
// 2x int4 neigh load + 32 coalesced mpi loads + 32 coalesced 2B h loads +
// 32 packed atomicMax. ~36 regs -> 6+ blocks/SM -> 2x the warps of the fused
// version feeding the atomic stream. Winner = largest v (reference sequential
// last-write-wins; collisions only within one (b,o) slice).
__global__ __launch_bounds__(256) void scatter_kernel(
    const int* __restrict__ mpi,
    unsigned int* __restrict__ out32)
{
    const int v = blockIdx.x * 256 + threadIdx.x;
    const int b = blockIdx.y;
    if (v >= V_LO) return;

    const int4* np = reinterpret_cast<const int4*>(&g_neigh8[v * 8]);
    int4 n0 = np[0];
    int4 n1 = np[1];
    int nb[8] = {n0.x, n0.y, n0.z, n0.w, n1.x, n1.y, n1.z, n1.w};

    const unsigned int vtag = ((unsigned int)(v + 1)) << 16;
    const int* mp = mpi + ((long long)b * C_OUT) * V_LO + v;
    const unsigned short* hp = g_h + ((long long)b * C_OUT) * V_LO + v;
    unsigned int* ob = out32 + ((long long)b * C_OUT) * V_HI;

#pragma unroll
    for (int o = 0; o < C_OUT; o++) {
        int k = __ldg(mp + (long long)o * V_LO);                 // coalesced
        unsigned int hb = __ldg(hp + (long long)o * V_LO);       // coalesced 2B
        int u = nb[k];
        atomicMax(&ob[(long long)o * V_HI + u], vtag | hb);      // RED.MAX.U32
    }
}

// In-place decode: 0 -> 0.0f, else float(fp16 low half). Vectorized uint4/float4.
__global__ __launch_bounds__(256) void finalize_kernel(unsigned int* __restrict__ buf,
                                                       long long n4)
{
    long long i = (long long)blockIdx.x * blockDim.x + threadIdx.x;
    if (i >= n4) return;
    uint4 p = reinterpret_cast<uint4*>(buf)[i];
    float4 f;
    f.x = p.x ? __half2float(__ushort_as_half((unsigned short)(p.x & 0xFFFFu))) : 0.0f;
    f.y = p.y ? __half2float(__ushort_as_half((unsigned short)(p.y & 0xFFFFu))) : 0.0f;
    f.z = p.z ? __half2float(__ushort_as_half((unsigned short)(p.z & 0xFFFFu))) : 0.0f;
    f.w = p.w ? __half2float(__ushort_as_half((unsigned short)(p.w & 0xFFFFu))) : 0.0f;
    reinterpret_cast<float4*>(buf)[i] = f;
}

extern "C" void kernel_launch(void* const* d_in, const int* in_sizes, int n_in,
                              void* d_out, int out_size) {
    const float* x    = (const float*)d_in[0];   // (16, 64, 40962) f32
    const float* W    = (const float*)d_in[1];   // (32, 64) f32
    const float* bias = (const float*)d_in[2];   // (32,) f32
    const int*   mpi  = (const int*)d_in[3];     // (16, 32, 40962) i32
    const int*   up   = (const int*)d_in[4];     // (163842, 7) i32
    const int*   down = (const int*)d_in[5];     // (40962,) i32

    unsigned int* out32 = (unsigned int*)d_out;  // aliases the f32 output buffer

    // 1) zero output (atomicMax identity)
    cudaMemsetAsync(d_out, 0, (size_t)out_size * sizeof(float), 0);

    // 2) build effective neighbor table
    build_neigh_kernel<<<(V_LO + 255) / 256, 256>>>(up, down);

    // 3) GEMV producer -> fp16 h scratch
    dim3 grid(TILES, BATCH);
    gemm_kernel<<<grid, 256>>>(x, W, bias);

    // 4) load-only packed atomicMax scatter (high warp count)
    scatter_kernel<<<grid, 256>>>(mpi, out32);

    // 5) in-place decode to float
    long long n4 = (long long)out_size / 4;
    finalize_kernel<<<(unsigned)((n4 + 255) / 256), 256>>>(out32, n4);
}

// round 13
// speedup vs baseline: 1.4222x; 1.4222x over previous
#include <cuda_runtime.h>
#include <cuda_fp16.h>

#define BATCH 16
#define C_IN  64
#define C_OUT 32
#define V_HI  163842
#define V_LO  40962
#define KNB   7

#define TILES ((V_LO + 255) / 256)   // 161 tiles of 256 vertices

// Precomputed neigh table: g_neigh8[v*8+k] = up_neigh[down[v]*7 + k], stride 8.
__device__ int g_neigh8[V_LO * 8];
// Nibble-packed max-pool indices: g_mpk[b*V_LO+v] = uint4, 4 bits per o (32 o's).
__device__ uint4 g_mpk[(long long)BATCH * V_LO];

// packed f32x2 FMA (sm_103a): d = a*b + c on two lanes.
#define FMA_F32X2(d, a, b, c) \
    asm("fma.rn.f32x2 %0, %1, %2, %3;" : "=l"(d) : "l"(a), "l"(b), "l"(c))
#define PACK_F32X2(out, lo, hi) \
    asm("mov.b64 %0, {%1, %2};" : "=l"(out) : "f"(lo), "f"(hi))
#define UNPACK_F32X2(lo, hi, in) \
    asm("mov.b64 {%0, %1}, %2;" : "=f"(lo), "=f"(hi) : "l"(in))

__global__ void build_neigh_kernel(const int* __restrict__ up_neigh,
                                   const int* __restrict__ down) {
    int v = blockIdx.x * blockDim.x + threadIdx.x;
    if (v >= V_LO) return;
    int dv = down[v];
    const int* src = up_neigh + (long long)dv * KNB;
#pragma unroll
    for (int k = 0; k < KNB; k++) g_neigh8[v * 8 + k] = src[k];
    g_neigh8[v * 8 + 7] = 0;
}

// Pack mpi[b, o, v] (values 0..6) into 4-bit nibbles: one uint4 per (b, v).
// Reads coalesced per o; writes coalesced 16B.
__global__ __launch_bounds__(256) void pack_mpi_kernel(const int* __restrict__ mpi) {
    const int v = blockIdx.x * 256 + threadIdx.x;
    const int b = blockIdx.y;
    if (v >= V_LO) return;
    const int* mp = mpi + ((long long)b * C_OUT) * V_LO + v;
    unsigned int r[4] = {0u, 0u, 0u, 0u};
#pragma unroll
    for (int o = 0; o < C_OUT; o++) {
        unsigned int k = (unsigned int)__ldg(mp + (long long)o * V_LO);
        r[o >> 3] |= (k & 0xFu) << (4 * (o & 7));
    }
    g_mpk[(long long)b * V_LO + v] = make_uint4(r[0], r[1], r[2], r[3]);
}

// Fused GEMV (f32x2-packed) + packed-atomicMax scatter. R1 structure; per
// thread: 64 x-loads, ~1100 FMA2-class ops (vs 2048 FFMA), ONE uint4 mpi load
// (vs 32 LDG), 32 RED.MAX.U32. Winner = largest v (reference sequential
// last-write-wins; collisions only within one (b,o) slice).
__global__ __launch_bounds__(256) void fused_gemm_scatter_kernel(
    const float* __restrict__ x,
    const float* __restrict__ W,
    const float* __restrict__ bias,
    unsigned int* __restrict__ out32)
{
    // sW2[c][p] = (W[2p][c], W[2p+1][c]) as one 64-bit word (broadcast LDS.64)
    __shared__ unsigned long long sW2[C_IN][C_OUT / 2];
    __shared__ float sB[C_OUT];

    const int tid = threadIdx.x;
    for (int i = tid; i < C_IN * (C_OUT / 2); i += 256) {
        int p = i / C_IN;           // o-pair
        int c = i % C_IN;
        float lo = W[(2 * p) * C_IN + c];
        float hi = W[(2 * p + 1) * C_IN + c];
        unsigned long long w;
        PACK_F32X2(w, lo, hi);
        sW2[c][p] = w;
    }
    if (tid < C_OUT) sB[tid] = bias[tid];
    __syncthreads();

    const int v = blockIdx.x * 256 + tid;
    const int b = blockIdx.y;
    if (v >= V_LO) return;

    // 16 packed accumulators = 32 channels
    unsigned long long h2[C_OUT / 2];
#pragma unroll
    for (int p = 0; p < C_OUT / 2; p++) {
        PACK_F32X2(h2[p], sB[2 * p], sB[2 * p + 1]);
    }

    const float* xp = x + ((long long)b * C_IN) * V_LO + v;
#pragma unroll
    for (int c = 0; c < C_IN; c++) {
        float xc = __ldg(xp + (long long)c * V_LO);
        unsigned long long xx;
        PACK_F32X2(xx, xc, xc);
#pragma unroll
        for (int p = 0; p < C_OUT / 2; p++) {
            FMA_F32X2(h2[p], xx, sW2[c][p], h2[p]);
        }
    }

    // Unpack to 32 floats
    float h[C_OUT];
#pragma unroll
    for (int p = 0; p < C_OUT / 2; p++) {
        UNPACK_F32X2(h[2 * p], h[2 * p + 1], h2[p]);
    }

    // 7 neighbor ids (two coalesced int4 loads)
    const int4* np = reinterpret_cast<const int4*>(&g_neigh8[v * 8]);
    int4 n0 = np[0];
    int4 n1 = np[1];
    int nb[8] = {n0.x, n0.y, n0.z, n0.w, n1.x, n1.y, n1.z, n1.w};

    // ONE uint4 load replaces 32 mpi LDGs
    const uint4 pk = __ldg(&g_mpk[(long long)b * V_LO + v]);
    const unsigned int pw[4] = {pk.x, pk.y, pk.z, pk.w};

    const unsigned int vtag = ((unsigned int)(v + 1)) << 16;
    unsigned int* ob = out32 + ((long long)b * C_OUT) * V_HI;

#pragma unroll
    for (int o = 0; o < C_OUT; o++) {
        int k = (int)((pw[o >> 3] >> (4 * (o & 7))) & 0xFu);
        int u = nb[k];
        unsigned short hb = __half_as_ushort(__float2half_rn(h[o]));
        atomicMax(&ob[(long long)o * V_HI + u], vtag | (unsigned int)hb);
    }
}

// In-place decode: 0 -> 0.0f, else float(fp16 low half). Vectorized uint4/float4.
__global__ __launch_bounds__(256) void finalize_kernel(unsigned int* __restrict__ buf,
                                                       long long n4)
{
    long long i = (long long)blockIdx.x * blockDim.x + threadIdx.x;
    if (i >= n4) return;
    uint4 p = reinterpret_cast<uint4*>(buf)[i];
    float4 f;
    f.x = p.x ? __half2float(__ushort_as_half((unsigned short)(p.x & 0xFFFFu))) : 0.0f;
    f.y = p.y ? __half2float(__ushort_as_half((unsigned short)(p.y & 0xFFFFu))) : 0.0f;
    f.z = p.z ? __half2float(__ushort_as_half((unsigned short)(p.z & 0xFFFFu))) : 0.0f;
    f.w = p.w ? __half2float(__ushort_as_half((unsigned short)(p.w & 0xFFFFu))) : 0.0f;
    reinterpret_cast<float4*>(buf)[i] = f;
}

extern "C" void kernel_launch(void* const* d_in, const int* in_sizes, int n_in,
                              void* d_out, int out_size) {
    const float* x    = (const float*)d_in[0];   // (16, 64, 40962) f32
    const float* W    = (const float*)d_in[1];   // (32, 64) f32
    const float* bias = (const float*)d_in[2];   // (32,) f32
    const int*   mpi  = (const int*)d_in[3];     // (16, 32, 40962) i32
    const int*   up   = (const int*)d_in[4];     // (163842, 7) i32
    const int*   down = (const int*)d_in[5];     // (40962,) i32

    unsigned int* out32 = (unsigned int*)d_out;  // aliases the f32 output buffer

    // 1) zero output (atomicMax identity)
    cudaMemsetAsync(d_out, 0, (size_t)out_size * sizeof(float), 0);

    // 2) build neighbor table + nibble-pack mpi
    build_neigh_kernel<<<(V_LO + 255) / 256, 256>>>(up, down);
    dim3 grid(TILES, BATCH);
    pack_mpi_kernel<<<grid, 256>>>(mpi);

    // 3) fused f32x2 GEMV + packed atomicMax scatter (one full-width launch)
    fused_gemm_scatter_kernel<<<grid, 256>>>(x, W, bias, out32);

    // 4) in-place decode to float
    long long n4 = (long long)out_size / 4;
    finalize_kernel<<<(unsigned)((n4 + 255) / 256), 256>>>(out32, n4);
}

// round 14
// speedup vs baseline: 1.4900x; 1.0477x over previous
#include <cuda_runtime.h>
#include <cuda_fp16.h>

#define BATCH 16
#define C_IN  64
#define C_OUT 32
#define V_HI  163842
#define V_LO  40962
#define KNB   7

#define TILES ((V_LO + 255) / 256)   // 161 tiles of 256 vertices

// Precomputed neigh table: g_neigh8[v*8+k] = up_neigh[down[v]*7 + k], stride 8.
__device__ int g_neigh8[V_LO * 8];

__global__ void build_neigh_kernel(const int* __restrict__ up_neigh,
                                   const int* __restrict__ down) {
    int v = blockIdx.x * blockDim.x + threadIdx.x;
    if (v >= V_LO) return;
    int dv = down[v];
    const int* src = up_neigh + (long long)dv * KNB;
#pragma unroll
    for (int k = 0; k < KNB; k++) g_neigh8[v * 8 + k] = src[k];
    g_neigh8[v * 8 + 7] = 0;
}

// Fused GEMV + packed-atomicMax scatter (R1-proven, best known).
// h[b,:,v] = W @ x[b,:,v] + bias; for each o:
//   u = neigh[v][mpi[b,o,v]];  atomicMax(out32[b,o,u], ((v+1)<<16) | fp16(h[o]))
// Winner = largest v (matches reference sequential-scatter last-write-wins;
// collisions only occur within one (b,o) slice).
__global__ __launch_bounds__(256) void fused_gemm_scatter_kernel(
    const float* __restrict__ x,
    const float* __restrict__ W,
    const float* __restrict__ bias,
    const int*   __restrict__ mpi,
    unsigned int* __restrict__ out32)
{
    __shared__ float sW[C_IN][C_OUT + 1];   // transposed, padded
    __shared__ float sB[C_OUT];

    int tid = threadIdx.x;
    for (int i = tid; i < C_IN * C_OUT; i += 256) {
        int o = i / C_IN;
        int c = i % C_IN;
        sW[c][o] = W[i];
    }
    if (tid < C_OUT) sB[tid] = bias[tid];
    __syncthreads();

    int v = blockIdx.x * 256 + tid;
    int b = blockIdx.y;
    if (v >= V_LO) return;

    // GEMV slice: h[o] = bias[o] + sum_c W[o][c] * x[b][c][v]
    float h[C_OUT];
#pragma unroll
    for (int o = 0; o < C_OUT; o++) h[o] = sB[o];

    const float* xp = x + ((long long)b * C_IN) * V_LO + v;
#pragma unroll
    for (int c = 0; c < C_IN; c++) {
        float xc = __ldg(xp + (long long)c * V_LO);
#pragma unroll
        for (int o = 0; o < C_OUT; o++) h[o] = fmaf(xc, sW[c][o], h[o]);
    }

    // Pack (v+1) in high 16 bits, fp16 value in low 16 bits.
    unsigned int vtag = ((unsigned int)(v + 1)) << 16;
    unsigned int ph[C_OUT];
#pragma unroll
    for (int o = 0; o < C_OUT; o++) {
        unsigned short hb = __half_as_ushort(__float2half_rn(h[o]));
        ph[o] = vtag | (unsigned int)hb;
    }

    // 7 neighbor ids for this v (contiguous 32B, coalesced across threads).
    const int4* np = reinterpret_cast<const int4*>(&g_neigh8[v * 8]);
    int4 n0 = np[0];
    int4 n1 = np[1];
    int nb[8] = {n0.x, n0.y, n0.z, n0.w, n1.x, n1.y, n1.z, n1.w};

    const int* mp = mpi + ((long long)b * C_OUT) * V_LO + v;
    unsigned int* ob = out32 + ((long long)b * C_OUT) * V_HI;

#pragma unroll
    for (int o = 0; o < C_OUT; o++) {
        int k = __ldg(mp + (long long)o * V_LO);   // coalesced
        int u = nb[k];
        atomicMax(&ob[(long long)o * V_HI + u], ph[o]);  // RED.MAX.U32
    }
}

// In-place decode: 0 -> 0.0f (already zero from memset -> SKIP the write),
// else float(fp16 low half). Writes only uint4s containing a nonzero word
// (~63%), cutting finalize write traffic 335 -> ~211 MB.
__global__ __launch_bounds__(256) void finalize_kernel(unsigned int* __restrict__ buf,
                                                       long long n4)
{
    long long i = (long long)blockIdx.x * blockDim.x + threadIdx.x;
    if (i >= n4) return;
    uint4 p = reinterpret_cast<uint4*>(buf)[i];
    if ((p.x | p.y | p.z | p.w) == 0u) return;   // slot group untouched: stays zero
    float4 f;
    f.x = p.x ? __half2float(__ushort_as_half((unsigned short)(p.x & 0xFFFFu))) : 0.0f;
    f.y = p.y ? __half2float(__ushort_as_half((unsigned short)(p.y & 0xFFFFu))) : 0.0f;
    f.z = p.z ? __half2float(__ushort_as_half((unsigned short)(p.z & 0xFFFFu))) : 0.0f;
    f.w = p.w ? __half2float(__ushort_as_half((unsigned short)(p.w & 0xFFFFu))) : 0.0f;
    reinterpret_cast<float4*>(buf)[i] = f;
}

extern "C" void kernel_launch(void* const* d_in, const int* in_sizes, int n_in,
                              void* d_out, int out_size) {
    const float* x    = (const float*)d_in[0];   // (16, 64, 40962) f32
    const float* W    = (const float*)d_in[1];   // (32, 64) f32
    const float* bias = (const float*)d_in[2];   // (32,) f32
    const int*   mpi  = (const int*)d_in[3];     // (16, 32, 40962) i32
    const int*   up   = (const int*)d_in[4];     // (163842, 7) i32
    const int*   down = (const int*)d_in[5];     // (40962,) i32

    unsigned int* out32 = (unsigned int*)d_out;  // aliases the f32 output buffer

    // 1) zero output (atomicMax identity; also provides the zeros finalize skips)
    cudaMemsetAsync(d_out, 0, (size_t)out_size * sizeof(float), 0);

    // 2) build effective neighbor table
    build_neigh_kernel<<<(V_LO + 255) / 256, 256>>>(up, down);

    // 3) fused GEMV + packed atomicMax scatter (one full-width launch)
    dim3 grid(TILES, BATCH);
    fused_gemm_scatter_kernel<<<grid, 256>>>(x, W, bias, mpi, out32);

    // 4) in-place decode to float (zero-skipping writes)
    long long n4 = (long long)out_size / 4;
    finalize_kernel<<<(unsigned)((n4 + 255) / 256), 256>>>(out32, n4);
}

// round 15
// speedup vs baseline: 1.5023x; 1.0083x over previous
#include <cuda_runtime.h>
#include <cuda_fp16.h>

#define BATCH 16
#define C_IN  64
#define C_OUT 32
#define V_HI  163842
#define V_LO  40962
#define KNB   7

#define TILES ((V_LO + 255) / 256)        // 161 tiles of 256 vertices
#define NEIGH_BLOCKS ((V_LO + 255) / 256) // 161
#define OUT_ELEMS ((long long)BATCH * C_OUT * V_HI)   // 83,886,

#define OUT_U4 (OUT_ELEMS / 4)            // 20,971,776... (divisible: 83886084? compute below)

// Precomputed neigh table: g_neigh8[v*8+k] = up_neigh[down[v]*7 + k], stride 8.
__device__ int g_neigh8[V_LO * 8];

// Prolog: blocks [0,161) build the neighbor table; the rest zero d_out
// (atomicMax identity) with coalesced uint4 stores at streaming bandwidth.
__global__ __launch_bounds__(256) void prolog_kernel(
    const int* __restrict__ up_neigh,
    const int* __restrict__ down,
    unsigned int* __restrict__ out32,
    long long n4)
{
    if (blockIdx.x < NEIGH_BLOCKS) {
        int v = blockIdx.x * 256 + threadIdx.x;
        if (v >= V_LO) return;
        int dv = down[v];
        const int* src = up_neigh + (long long)dv * KNB;
#pragma unroll
        for (int k = 0; k < KNB; k++) g_neigh8[v * 8 + k] = src[k];
        g_neigh8[v * 8 + 7] = 0;
    } else {
        long long i = (long long)(blockIdx.x - NEIGH_BLOCKS) * 256 + threadIdx.x;
        if (i >= n4) return;
        reinterpret_cast<uint4*>(out32)[i] = make_uint4(0u, 0u, 0u, 0u);
    }
}

// atomicMax (RED.MAX.U32) with L2 evict_last retention hint: raises the chance
// that a later atomic to the same 32B sector hits L2 before eviction.
__device__ __forceinline__ void red_max_evict_last(unsigned int* addr, unsigned int val,
                                                   unsigned long long policy) {
    asm volatile("red.global.L2::cache_hint.max.u32 [%0], %1, %2;"
                 :: "l"(addr), "r"(val), "l"(policy) : "memory");
}

// Fused GEMV + packed-atomicMax scatter (R1-proven body).
// h[b,:,v] = W @ x[b,:,v] + bias; for each o:
//   u = neigh[v][mpi[b,o,v]];  redMax(out32[b,o,u], ((v+1)<<16) | fp16(h[o]))
// Winner = largest v (matches reference sequential-scatter last-write-wins;
// collisions only occur within one (b,o) slice).
__global__ __launch_bounds__(256) void fused_gemm_scatter_kernel(
    const float* __restrict__ x,
    const float* __restrict__ W,
    const float* __restrict__ bias,
    const int*   __restrict__ mpi,
    unsigned int* __restrict__ out32)
{
    __shared__ float sW[C_IN][C_OUT + 1];   // transposed, padded
    __shared__ float sB[C_OUT];

    int tid = threadIdx.x;
    for (int i = tid; i < C_IN * C_OUT; i += 256) {
        int o = i / C_IN;
        int c = i % C_IN;
        sW[c][o] = W[i];
    }
    if (tid < C_OUT) sB[tid] = bias[tid];
    __syncthreads();

    int v = blockIdx.x * 256 + tid;
    int b = blockIdx.y;
    if (v >= V_LO) return;

    // GEMV slice: h[o] = bias[o] + sum_c W[o][c] * x[b][c][v]
    float h[C_OUT];
#pragma unroll
    for (int o = 0; o < C_OUT; o++) h[o] = sB[o];

    const float* xp = x + ((long long)b * C_IN) * V_LO + v;
#pragma unroll
    for (int c = 0; c < C_IN; c++) {
        float xc = __ldg(xp + (long long)c * V_LO);
#pragma unroll
        for (int o = 0; o < C_OUT; o++) h[o] = fmaf(xc, sW[c][o], h[o]);
    }

    // Pack (v+1) in high 16 bits, fp16 value in low 16 bits.
    unsigned int vtag = ((unsigned int)(v + 1)) << 16;
    unsigned int ph[C_OUT];
#pragma unroll
    for (int o = 0; o < C_OUT; o++) {
        unsigned short hb = __half_as_ushort(__float2half_rn(h[o]));
        ph[o] = vtag | (unsigned int)hb;
    }

    // 7 neighbor ids for this v (contiguous 32B, coalesced across threads).
    const int4* np = reinterpret_cast<const int4*>(&g_neigh8[v * 8]);
    int4 n0 = np[0];
    int4 n1 = np[1];
    int nb[8] = {n0.x, n0.y, n0.z, n0.w, n1.x, n1.y, n1.z, n1.w};

    unsigned long long policy;
    asm("createpolicy.fractional.L2::evict_last.b64 %0, 1.0;" : "=l"(policy));

    const int* mp = mpi + ((long long)b * C_OUT) * V_LO + v;
    unsigned int* ob = out32 + ((long long)b * C_OUT) * V_HI;

#pragma unroll
    for (int o = 0; o < C_OUT; o++) {
        int k = __ldg(mp + (long long)o * V_LO);   // coalesced
        int u = nb[k];
        red_max_evict_last(&ob[(long long)o * V_HI + u], ph[o], policy);
    }
}

// In-place decode: 0 -> 0.0f (already zero from prolog -> SKIP the write),
// else float(fp16 low half). Writes only uint4s containing a nonzero word.
__global__ __launch_bounds__(256) void finalize_kernel(unsigned int* __restrict__ buf,
                                                       long long n4)
{
    long long i = (long long)blockIdx.x * blockDim.x + threadIdx.x;
    if (i >= n4) return;
    uint4 p = reinterpret_cast<uint4*>(buf)[i];
    if ((p.x | p.y | p.z | p.w) == 0u) return;   // untouched group: stays zero
    float4 f;
    f.x = p.x ? __half2float(__ushort_as_half((unsigned short)(p.x & 0xFFFFu))) : 0.0f;
    f.y = p.y ? __half2float(__ushort_as_half((unsigned short)(p.y & 0xFFFFu))) : 0.0f;
    f.z = p.z ? __half2float(__ushort_as_half((unsigned short)(p.z & 0xFFFFu))) : 0.0f;
    f.w = p.w ? __half2float(__ushort_as_half((unsigned short)(p.w & 0xFFFFu))) : 0.0f;
    reinterpret_cast<float4*>(buf)[i] = f;
}

extern "C" void kernel_launch(void* const* d_in, const int* in_sizes, int n_in,
                              void* d_out, int out_size) {
    const float* x    = (const float*)d_in[0];   // (16, 64, 40962) f32
    const float* W    = (const float*)d_in[1];   // (32, 64) f32
    const float* bias = (const float*)d_in[2];   // (32,) f32
    const int*   mpi  = (const int*)d_in[3];     // (16, 32, 40962) i32
    const int*   up   = (const int*)d_in[4];     // (163842, 7) i32
    const int*   down = (const int*)d_in[5];     // (40962,) i32

    unsigned int* out32 = (unsigned int*)d_out;  // aliases the f32 output buffer

    long long n4 = (long long)out_size / 4;
    unsigned fin_grid = (unsigned)((n4 + 255) / 256);

    // 1) heterogeneous prolog: build neigh table + zero output, one launch
    prolog_kernel<<<NEIGH_BLOCKS + fin_grid, 256>>>(up, down, out32, n4);

    // 2) fused GEMV + packed atomicMax scatter (one full-width launch)
    dim3 grid(TILES, BATCH);
    fused_gemm_scatter_kernel<<<grid, 256>>>(x, W, bias, mpi, out32);

    // 3) in-place decode to float (zero-skipping writes)
    finalize_kernel<<<fin_grid, 256>>>(out32, n4);
}